// round 1
// baseline (speedup 1.0000x reference)
#include <cuda_runtime.h>
#include <cuda_bf16.h>

// Problem constants
#define BB 2
#define TT 1024
#define CC 768
#define HH 12
#define DH 64
#define LL 4
#define HID 3072
#define VV 32000
#define BT (BB*TT)          // 2048
#define QKVN (3*CC)         // 2304

// ---------------- scratch (device globals; no cudaMalloc allowed) ----------
__device__ float g_x[BT*CC];        // residual stream
__device__ float g_h[BT*CC];        // layernorm output
__device__ float g_qkv[BT*QKVN];    // fused qkv output
__device__ float g_attn[BT*CC];     // attention output (concat heads)
__device__ float g_hid[BT*HID];     // MLP hidden
__device__ float g_wqkv[LL*CC*QKVN];// packed qkv weights per layer
__device__ float g_rowloss[BT];     // per-row -logp[target]

// ---------------- weight packing: Wq/Wk/Wv [L,H,C,DH] -> [L][C][3C] --------
__global__ void pack_qkv_kernel(const float* __restrict__ Wq,
                                const float* __restrict__ Wk,
                                const float* __restrict__ Wv) {
    const long total = (long)LL * CC * QKVN;
    for (long i = (long)blockIdx.x * blockDim.x + threadIdx.x; i < total;
         i += (long)gridDim.x * blockDim.x) {
        int n = (int)(i % QKVN);
        long r = i / QKVN;
        int k = (int)(r % CC);
        int l = (int)(r / CC);
        const float* W; int nn = n;
        if (n < CC)           { W = Wq; }
        else if (n < 2*CC)    { W = Wk; nn = n - CC; }
        else                  { W = Wv; nn = n - 2*CC; }
        int h = nn >> 6, d = nn & 63;
        g_wqkv[i] = W[(((long)l*HH + h)*CC + k)*DH + d];
    }
}

// ---------------- embedding: x = tok_emb[idx] + pos_emb[:T] ----------------
__global__ void embed_kernel(const int* __restrict__ idx,
                             const float* __restrict__ tok,
                             const float* __restrict__ pos) {
    int i = blockIdx.x * blockDim.x + threadIdx.x;
    if (i >= BT*CC) return;
    int c = i % CC;
    int bt = i / CC;
    int t = bt % TT;
    g_x[i] = tok[(long)idx[bt]*CC + c] + pos[(long)t*CC + c];
}

// ---------------- layernorm: one block per row -----------------------------
__global__ void layernorm_kernel(const float* __restrict__ x,
                                 const float* __restrict__ g,
                                 const float* __restrict__ b,
                                 float* __restrict__ y) {
    __shared__ float rs[256], rs2[256];
    int row = blockIdx.x;
    const float* xr = x + (long)row*CC;
    float s = 0.f, s2 = 0.f;
    for (int c = threadIdx.x; c < CC; c += 256) {
        float v = xr[c];
        s += v; s2 += v*v;
    }
    rs[threadIdx.x] = s; rs2[threadIdx.x] = s2;
    __syncthreads();
    for (int o = 128; o > 0; o >>= 1) {
        if (threadIdx.x < o) {
            rs[threadIdx.x]  += rs[threadIdx.x + o];
            rs2[threadIdx.x] += rs2[threadIdx.x + o];
        }
        __syncthreads();
    }
    float mean = rs[0] * (1.f/CC);
    float var  = rs2[0] * (1.f/CC) - mean*mean;
    float inv  = rsqrtf(var + 1e-5f);
    for (int c = threadIdx.x; c < CC; c += 256) {
        y[(long)row*CC + c] = (xr[c] - mean) * inv * g[c] + b[c];
    }
}

// ---------------- SGEMM: C = A[M,K] * B[K,N] (+bias)(+res)(relu) -----------
// BM=BN=128, BK=16, 256 threads, 8x8 per-thread microtile.
// All M,N,K used are exact multiples of the tiles -> no bounds checks.
template<bool BIAS, bool RELU, bool RES>
__global__ void __launch_bounds__(256)
sgemm_kernel(const float* __restrict__ A, const float* __restrict__ B,
             const float* __restrict__ bias, const float* __restrict__ res,
             float* __restrict__ C, int M, int N, int K) {
    __shared__ float As[16][128];
    __shared__ float Bs[16][128];
    const int tid = threadIdx.x;
    const int m0 = blockIdx.y * 128;
    const int n0 = blockIdx.x * 128;
    const int tx = tid & 15;     // 0..15 -> n micro
    const int ty = tid >> 4;     // 0..15 -> m micro
    float acc[8][8];
    #pragma unroll
    for (int i = 0; i < 8; i++)
        #pragma unroll
        for (int j = 0; j < 8; j++) acc[i][j] = 0.f;

    const int aRow = tid >> 2;          // 0..63
    const int aCol = (tid & 3) * 4;     // 0,4,8,12
    const int bRow = tid >> 5;          // 0..7
    const int bCol = (tid & 31) * 4;    // 0..124

    const float* Ab = A + (long)m0 * K;
    const float* Bb = B + n0;

    for (int k0 = 0; k0 < K; k0 += 16) {
        #pragma unroll
        for (int r = 0; r < 2; r++) {
            int row = aRow + r*64;
            float4 v = *(const float4*)(Ab + (long)row*K + k0 + aCol);
            As[aCol+0][row] = v.x;
            As[aCol+1][row] = v.y;
            As[aCol+2][row] = v.z;
            As[aCol+3][row] = v.w;
        }
        #pragma unroll
        for (int r = 0; r < 2; r++) {
            int row = bRow + r*8;
            float4 v = *(const float4*)(Bb + (long)(k0+row)*N + bCol);
            *(float4*)&Bs[row][bCol] = v;
        }
        __syncthreads();
        #pragma unroll
        for (int k = 0; k < 16; k++) {
            float ra[8], rb[8];
            #pragma unroll
            for (int i = 0; i < 8; i++) ra[i] = As[k][ty*8 + i];
            #pragma unroll
            for (int j = 0; j < 8; j++) rb[j] = Bs[k][tx*8 + j];
            #pragma unroll
            for (int i = 0; i < 8; i++)
                #pragma unroll
                for (int j = 0; j < 8; j++)
                    acc[i][j] += ra[i] * rb[j];
        }
        __syncthreads();
    }

    #pragma unroll
    for (int i = 0; i < 8; i++) {
        long row = m0 + ty*8 + i;
        #pragma unroll
        for (int j = 0; j < 8; j++) {
            int col = n0 + tx*8 + j;
            float v = acc[i][j];
            if (BIAS) v += bias[col];
            if (RES)  v += res[row*N + col];
            if (RELU) v = fmaxf(v, 0.f);
            C[row*N + col] = v;
        }
    }
}

// ---------------- fused causal attention: one block per (b,h,t) ------------
// qkv layout: [BT, 3C], q at col h*64+d, k at 768+h*64+d, v at 1536+h*64+d.
__global__ void attention_kernel(const float* __restrict__ qkv,
                                 float* __restrict__ out) {
    __shared__ float qs[DH];
    __shared__ float sc[TT];
    __shared__ float red[128];
    const int t  = blockIdx.x;
    const int bh = blockIdx.y;
    const int b  = bh / HH;
    const int h  = bh % HH;
    const int tid = threadIdx.x;          // 128 threads
    const float* base = qkv + (long)b*TT*QKVN;

    if (tid < DH) qs[tid] = base[(long)t*QKVN + h*DH + tid];
    __syncthreads();

    // pass 1: scores + max
    float lmax = -1e30f;
    for (int s = tid; s <= t; s += 128) {
        const float4* kr = (const float4*)(base + (long)s*QKVN + CC + h*DH);
        float d = 0.f;
        #pragma unroll
        for (int j = 0; j < DH/4; j++) {
            float4 kv = kr[j];
            d += qs[4*j+0]*kv.x + qs[4*j+1]*kv.y + qs[4*j+2]*kv.z + qs[4*j+3]*kv.w;
        }
        d *= 0.125f;   // DH^-0.5
        sc[s] = d;
        lmax = fmaxf(lmax, d);
    }
    red[tid] = lmax; __syncthreads();
    for (int o = 64; o > 0; o >>= 1) {
        if (tid < o) red[tid] = fmaxf(red[tid], red[tid+o]);
        __syncthreads();
    }
    float m = red[0]; __syncthreads();

    // pass 2: exp + sum
    float lsum = 0.f;
    for (int s = tid; s <= t; s += 128) {
        float p = expf(sc[s] - m);
        sc[s] = p;
        lsum += p;
    }
    red[tid] = lsum; __syncthreads();
    for (int o = 64; o > 0; o >>= 1) {
        if (tid < o) red[tid] += red[tid+o];
        __syncthreads();
    }
    float inv = 1.0f / red[0]; __syncthreads();

    // pass 3: o[d] = sum_s p[s] * v[s][d] ; 2 s-chunks of 64 threads
    const int d     = tid & 63;
    const int chunk = tid >> 6;
    float acc = 0.f;
    const float* vb = base + 2*CC + h*DH + d;
    for (int s = chunk; s <= t; s += 2) {
        acc += sc[s] * vb[(long)s*QKVN];
    }
    red[tid] = acc; __syncthreads();
    if (chunk == 0) {
        out[((long)b*TT + t)*CC + h*DH + d] = (red[tid] + red[tid+64]) * inv;
    }
}

// ---------------- cross-entropy: per-row -logp[target] ---------------------
__global__ void loss_rows_kernel(const float* __restrict__ logits,
                                 const int* __restrict__ targets) {
    __shared__ float red[256];
    const int row = blockIdx.x;
    const float* lr = logits + (long)row*VV;
    float lmax = -1e30f;
    for (int c = threadIdx.x; c < VV; c += 256) lmax = fmaxf(lmax, lr[c]);
    red[threadIdx.x] = lmax; __syncthreads();
    for (int o = 128; o > 0; o >>= 1) {
        if (threadIdx.x < o) red[threadIdx.x] = fmaxf(red[threadIdx.x], red[threadIdx.x+o]);
        __syncthreads();
    }
    float m = red[0]; __syncthreads();
    float s = 0.f;
    for (int c = threadIdx.x; c < VV; c += 256) s += expf(lr[c] - m);
    red[threadIdx.x] = s; __syncthreads();
    for (int o = 128; o > 0; o >>= 1) {
        if (threadIdx.x < o) red[threadIdx.x] += red[threadIdx.x+o];
        __syncthreads();
    }
    if (threadIdx.x == 0) {
        float lse = m + logf(red[0]);
        g_rowloss[row] = lse - lr[targets[row]];
    }
}

__global__ void loss_reduce_kernel(float* __restrict__ out) {
    __shared__ float red[256];
    float s = 0.f;
    for (int i = threadIdx.x; i < BT; i += 256) s += g_rowloss[i];
    red[threadIdx.x] = s; __syncthreads();
    for (int o = 128; o > 0; o >>= 1) {
        if (threadIdx.x < o) red[threadIdx.x] += red[threadIdx.x+o];
        __syncthreads();
    }
    if (threadIdx.x == 0) *out = red[0] * (1.0f/BT);
}

// ---------------- driver ----------------------------------------------------
extern "C" void kernel_launch(void* const* d_in, const int* in_sizes, int n_in,
                              void* d_out, int out_size) {
    const int*   idx     = (const int*)  d_in[0];
    const int*   targets = (const int*)  d_in[1];
    const float* tok_emb = (const float*)d_in[2];
    const float* pos_emb = (const float*)d_in[3];
    const float* Wq      = (const float*)d_in[4];
    const float* Wk      = (const float*)d_in[5];
    const float* Wv      = (const float*)d_in[6];
    const float* Wproj   = (const float*)d_in[7];
    const float* bproj   = (const float*)d_in[8];
    const float* ln1_g   = (const float*)d_in[9];
    const float* ln1_b   = (const float*)d_in[10];
    const float* ln2_g   = (const float*)d_in[11];
    const float* ln2_b   = (const float*)d_in[12];
    const float* W1      = (const float*)d_in[13];
    const float* b1      = (const float*)d_in[14];
    const float* W2      = (const float*)d_in[15];
    const float* b2      = (const float*)d_in[16];
    const float* Wlm     = (const float*)d_in[17];
    const float* blm     = (const float*)d_in[18];
    float* out = (float*)d_out;

    float* xp;    cudaGetSymbolAddress((void**)&xp,    g_x);
    float* hp;    cudaGetSymbolAddress((void**)&hp,    g_h);
    float* qkvp;  cudaGetSymbolAddress((void**)&qkvp,  g_qkv);
    float* attnp; cudaGetSymbolAddress((void**)&attnp, g_attn);
    float* hidp;  cudaGetSymbolAddress((void**)&hidp,  g_hid);
    float* wqkvp; cudaGetSymbolAddress((void**)&wqkvp, g_wqkv);

    pack_qkv_kernel<<<4096, 256>>>(Wq, Wk, Wv);
    embed_kernel<<<(BT*CC + 255)/256, 256>>>(idx, tok_emb, pos_emb);

    for (int l = 0; l < LL; l++) {
        layernorm_kernel<<<BT, 256>>>(xp, ln1_g + l*CC, ln1_b + l*CC, hp);

        // qkv = h @ Wqkv_packed[l]    [2048,768] x [768,2304]
        sgemm_kernel<false,false,false><<<dim3(QKVN/128, BT/128), 256>>>(
            hp, wqkvp + (long)l*CC*QKVN, nullptr, nullptr, qkvp, BT, QKVN, CC);

        attention_kernel<<<dim3(TT, BB*HH), 128>>>(qkvp, attnp);

        // x = x + attn @ Wproj[l] + bproj[l]
        sgemm_kernel<true,false,true><<<dim3(CC/128, BT/128), 256>>>(
            attnp, Wproj + (long)l*CC*CC, bproj + l*CC, xp, xp, BT, CC, CC);

        layernorm_kernel<<<BT, 256>>>(xp, ln2_g + l*CC, ln2_b + l*CC, hp);

        // hid = relu(h @ W1[l] + b1[l])
        sgemm_kernel<true,true,false><<<dim3(HID/128, BT/128), 256>>>(
            hp, W1 + (long)l*CC*HID, b1 + (long)l*HID, nullptr, hidp, BT, HID, CC);

        // x = x + hid @ W2[l] + b2[l]
        sgemm_kernel<true,false,true><<<dim3(CC/128, BT/128), 256>>>(
            hidp, W2 + (long)l*HID*CC, b2 + l*CC, xp, xp, BT, CC, HID);
    }

    // logits = x @ Wlm + blm  -> directly into d_out
    sgemm_kernel<true,false,false><<<dim3(VV/128, BT/128), 256>>>(
        xp, Wlm, blm, nullptr, out, BT, VV, CC);

    loss_rows_kernel<<<BT, 256>>>(out, targets);
    if (out_size >= BT*VV + 1) {
        loss_reduce_kernel<<<1, 256>>>(out + (long)BT*VV);
    } else if (out_size == 1) {
        loss_reduce_kernel<<<1, 256>>>(out);
    }
}

// round 2
// speedup vs baseline: 2.1787x; 2.1787x over previous
#include <cuda_runtime.h>
#include <cuda_bf16.h>
#include <cstdint>

// Problem constants
#define BB 2
#define TT 1024
#define CC 768
#define HH 12
#define DH 64
#define LL 4
#define HID 3072
#define VV 32000
#define BT (BB*TT)          // 2048
#define QKVN (3*CC)         // 2304

// ---------------- scratch (device globals; no cudaMalloc allowed) ----------
__device__ float g_x[BT*CC];        // residual stream
__device__ float g_h[BT*CC];        // layernorm output
__device__ float g_qkv[BT*QKVN];    // fused qkv output
__device__ float g_attn[BT*CC];     // attention output (concat heads)
__device__ float g_hid[BT*HID];     // MLP hidden
__device__ float g_wqkv[LL*CC*QKVN];// packed qkv weights per layer
__device__ float g_rowloss[BT];     // per-row -logp[target]

// ---------------- weight packing: Wq/Wk/Wv [L,H,C,DH] -> [L][C][3C] --------
__global__ void pack_qkv_kernel(const float* __restrict__ Wq,
                                const float* __restrict__ Wk,
                                const float* __restrict__ Wv) {
    const long total = (long)LL * CC * QKVN;
    for (long i = (long)blockIdx.x * blockDim.x + threadIdx.x; i < total;
         i += (long)gridDim.x * blockDim.x) {
        int n = (int)(i % QKVN);
        long r = i / QKVN;
        int k = (int)(r % CC);
        int l = (int)(r / CC);
        const float* W; int nn = n;
        if (n < CC)           { W = Wq; }
        else if (n < 2*CC)    { W = Wk; nn = n - CC; }
        else                  { W = Wv; nn = n - 2*CC; }
        int h = nn >> 6, d = nn & 63;
        g_wqkv[i] = W[(((long)l*HH + h)*CC + k)*DH + d];
    }
}

// ---------------- embedding: x = tok_emb[idx] + pos_emb[:T] ----------------
__global__ void embed_kernel(const int* __restrict__ idx,
                             const float* __restrict__ tok,
                             const float* __restrict__ pos) {
    int i = blockIdx.x * blockDim.x + threadIdx.x;
    if (i >= BT*CC) return;
    int c = i % CC;
    int bt = i / CC;
    int t = bt % TT;
    g_x[i] = tok[(long)idx[bt]*CC + c] + pos[(long)t*CC + c];
}

// ---------------- layernorm: one block per row -----------------------------
__global__ void layernorm_kernel(const float* __restrict__ x,
                                 const float* __restrict__ g,
                                 const float* __restrict__ b,
                                 float* __restrict__ y) {
    __shared__ float rs[256], rs2[256];
    int row = blockIdx.x;
    const float* xr = x + (long)row*CC;
    float s = 0.f, s2 = 0.f;
    for (int c = threadIdx.x; c < CC; c += 256) {
        float v = xr[c];
        s += v; s2 += v*v;
    }
    rs[threadIdx.x] = s; rs2[threadIdx.x] = s2;
    __syncthreads();
    for (int o = 128; o > 0; o >>= 1) {
        if (threadIdx.x < o) {
            rs[threadIdx.x]  += rs[threadIdx.x + o];
            rs2[threadIdx.x] += rs2[threadIdx.x + o];
        }
        __syncthreads();
    }
    float mean = rs[0] * (1.f/CC);
    float var  = rs2[0] * (1.f/CC) - mean*mean;
    float inv  = rsqrtf(var + 1e-5f);
    for (int c = threadIdx.x; c < CC; c += 256) {
        y[(long)row*CC + c] = (xr[c] - mean) * inv * g[c] + b[c];
    }
}

// ---------------- TF32 tensor-core GEMM -------------------------------------
// C[M,N] = A[M,K] * B[K,N] (+bias)(+res)(relu). fp32 I/O, tf32 mma, fp32 acc.
// BM=BN=128, BK=16, 256 threads = 8 warps in 4x2 grid; warp tile 32x64.
// mma.sync.aligned.m16n8k8.row.col.f32.tf32.tf32.f32
// All M,N,K used are exact multiples of the tiles -> no bounds checks.
#define ASTRIDE 20    // [m][k] padded: frag banks (20m+k)%32 conflict-free; 80B rows -> STS.128 ok
#define BSTRIDE 136   // [k][n] padded: frag banks (8k+n)%32 conflict-free; 544B rows -> STS.128 ok

__device__ __forceinline__ uint32_t f2tf32(float f) {
    uint32_t u;
    asm("cvt.rna.tf32.f32 %0, %1;" : "=r"(u) : "f"(f));
    return u;
}

template<bool BIAS, bool RELU, bool RES>
__global__ void __launch_bounds__(256)
gemm_tf32_kernel(const float* __restrict__ A, const float* __restrict__ B,
                 const float* __restrict__ bias, const float* __restrict__ res,
                 float* __restrict__ C, int M, int N, int K) {
    __shared__ uint32_t As[128 * ASTRIDE];
    __shared__ uint32_t Bs[16 * BSTRIDE];
    const int tid  = threadIdx.x;
    const int wid  = tid >> 5;
    const int lane = tid & 31;
    const int warpM = wid & 3;        // 0..3  -> 32-row slab
    const int warpN = wid >> 2;       // 0..1  -> 64-col slab
    const int gr = lane >> 2;         // 0..7
    const int gc = lane & 3;          // 0..3
    const int m0 = blockIdx.y * 128;
    const int n0 = blockIdx.x * 128;

    float acc[2][8][4];
    #pragma unroll
    for (int mi = 0; mi < 2; mi++)
        #pragma unroll
        for (int ni = 0; ni < 8; ni++)
            #pragma unroll
            for (int j = 0; j < 4; j++) acc[mi][ni][j] = 0.f;

    const int aRow = tid >> 2;          // 0..63
    const int aCol = (tid & 3) << 2;    // 0,4,8,12
    const int bRow = tid >> 5;          // 0..7
    const int bCol = (tid & 31) << 2;   // 0..124

    for (int k0 = 0; k0 < K; k0 += 16) {
        // stage A tile [128][16] -> As[m][k]
        #pragma unroll
        for (int r = 0; r < 2; r++) {
            int row = aRow + r*64;
            float4 v = *(const float4*)(A + (long)(m0+row)*K + k0 + aCol);
            uint4 u;
            u.x = f2tf32(v.x); u.y = f2tf32(v.y); u.z = f2tf32(v.z); u.w = f2tf32(v.w);
            *(uint4*)&As[row*ASTRIDE + aCol] = u;
        }
        // stage B tile [16][128] -> Bs[k][n]
        #pragma unroll
        for (int r = 0; r < 2; r++) {
            int krow = bRow + r*8;
            float4 v = *(const float4*)(B + (long)(k0+krow)*N + n0 + bCol);
            uint4 u;
            u.x = f2tf32(v.x); u.y = f2tf32(v.y); u.z = f2tf32(v.z); u.w = f2tf32(v.w);
            *(uint4*)&Bs[krow*BSTRIDE + bCol] = u;
        }
        __syncthreads();

        #pragma unroll
        for (int kc = 0; kc < 16; kc += 8) {
            uint32_t af[2][4];
            #pragma unroll
            for (int mi = 0; mi < 2; mi++) {
                int row = warpM*32 + mi*16 + gr;
                af[mi][0] = As[row*ASTRIDE + kc + gc];
                af[mi][1] = As[(row+8)*ASTRIDE + kc + gc];
                af[mi][2] = As[row*ASTRIDE + kc + gc + 4];
                af[mi][3] = As[(row+8)*ASTRIDE + kc + gc + 4];
            }
            uint32_t bf[8][2];
            #pragma unroll
            for (int ni = 0; ni < 8; ni++) {
                int col = warpN*64 + ni*8 + gr;
                bf[ni][0] = Bs[(kc+gc)*BSTRIDE + col];
                bf[ni][1] = Bs[(kc+gc+4)*BSTRIDE + col];
            }
            #pragma unroll
            for (int mi = 0; mi < 2; mi++)
                #pragma unroll
                for (int ni = 0; ni < 8; ni++)
                    asm volatile(
                        "mma.sync.aligned.m16n8k8.row.col.f32.tf32.tf32.f32 "
                        "{%0,%1,%2,%3},{%4,%5,%6,%7},{%8,%9},{%0,%1,%2,%3};"
                        : "+f"(acc[mi][ni][0]), "+f"(acc[mi][ni][1]),
                          "+f"(acc[mi][ni][2]), "+f"(acc[mi][ni][3])
                        : "r"(af[mi][0]), "r"(af[mi][1]),
                          "r"(af[mi][2]), "r"(af[mi][3]),
                          "r"(bf[ni][0]), "r"(bf[ni][1]));
        }
        __syncthreads();
    }

    // epilogue: c0,c1 at (row=gr, col=2gc..+1); c2,c3 at row gr+8
    #pragma unroll
    for (int mi = 0; mi < 2; mi++) {
        #pragma unroll
        for (int rr = 0; rr < 2; rr++) {
            long row = m0 + warpM*32 + mi*16 + gr + rr*8;
            #pragma unroll
            for (int ni = 0; ni < 8; ni++) {
                int col = n0 + warpN*64 + ni*8 + gc*2;
                float v0 = acc[mi][ni][rr*2+0];
                float v1 = acc[mi][ni][rr*2+1];
                if (BIAS) { v0 += bias[col]; v1 += bias[col+1]; }
                if (RES)  {
                    float2 rv = *(const float2*)(res + row*N + col);
                    v0 += rv.x; v1 += rv.y;
                }
                if (RELU) { v0 = fmaxf(v0, 0.f); v1 = fmaxf(v1, 0.f); }
                float2 ov; ov.x = v0; ov.y = v1;
                *(float2*)(C + row*N + col) = ov;
            }
        }
    }
}

// ---------------- flash attention: block = 64 queries of one (b,h) ---------
// qkv layout [BT, 3C]: q at col h*64+d, k at 768+h*64+d, v at 1536+h*64+d.
#define TQ 64
#define TS 16
__global__ void __launch_bounds__(TQ)
flash_attn_kernel(const float* __restrict__ qkv, float* __restrict__ out) {
    __shared__ float Ks[TS][DH];
    __shared__ float Vs[TS][DH];
    // launch longest blocks first (largest q0) to balance causal work
    const int q0 = (gridDim.x - 1 - blockIdx.x) * TQ;
    const int bh = blockIdx.y;
    const int b  = bh / HH;
    const int h  = bh % HH;
    const int tid = threadIdx.x;
    const int t = q0 + tid;
    const float* base = qkv + (long)b*TT*QKVN;

    float q[DH];
    {
        const float4* qr = (const float4*)(base + (long)t*QKVN + h*DH);
        #pragma unroll
        for (int j = 0; j < DH/4; j++) {
            float4 v = qr[j];
            q[4*j+0] = v.x; q[4*j+1] = v.y; q[4*j+2] = v.z; q[4*j+3] = v.w;
        }
    }
    float acc[DH];
    #pragma unroll
    for (int j = 0; j < DH; j++) acc[j] = 0.f;
    float m = -1e30f, l = 0.f;

    const int smax = q0 + TQ - 1;
    for (int s0 = 0; s0 <= smax; s0 += TS) {
        // cooperative load K/V tiles: TS*DH = 1024 floats = 256 float4 each
        #pragma unroll
        for (int i = 0; i < (TS*DH)/(TQ*4); i++) {
            int idx = tid + i*TQ;            // float4 index 0..255
            int s  = idx >> 4;               // /16 float4s per row
            int d4 = (idx & 15) << 2;
            const float* kp = base + (long)(s0+s)*QKVN + CC + h*DH + d4;
            const float* vp = base + (long)(s0+s)*QKVN + 2*CC + h*DH + d4;
            *(float4*)&Ks[s][d4] = *(const float4*)kp;
            *(float4*)&Vs[s][d4] = *(const float4*)vp;
        }
        __syncthreads();

        float sc[TS];
        float tmax = -1e30f;
        #pragma unroll
        for (int s = 0; s < TS; s++) {
            float d0 = 0.f, d1 = 0.f, d2 = 0.f, d3 = 0.f;
            #pragma unroll
            for (int j = 0; j < DH; j += 4) {
                d0 += q[j+0] * Ks[s][j+0];
                d1 += q[j+1] * Ks[s][j+1];
                d2 += q[j+2] * Ks[s][j+2];
                d3 += q[j+3] * Ks[s][j+3];
            }
            float d = (d0 + d1) + (d2 + d3);
            sc[s] = (s0 + s <= t) ? d * 0.125f : -1e30f;
            tmax = fmaxf(tmax, sc[s]);
        }
        float m_new = fmaxf(m, tmax);
        float alpha = __expf(m - m_new);
        l *= alpha;
        #pragma unroll
        for (int j = 0; j < DH; j++) acc[j] *= alpha;
        #pragma unroll
        for (int s = 0; s < TS; s++) {
            float p = __expf(sc[s] - m_new);
            l += p;
            #pragma unroll
            for (int j = 0; j < DH; j++) acc[j] += p * Vs[s][j];
        }
        m = m_new;
        __syncthreads();
    }

    float inv = 1.0f / l;
    float* o = out + ((long)b*TT + t)*CC + h*DH;
    #pragma unroll
    for (int j = 0; j < DH/4; j++) {
        float4 v;
        v.x = acc[4*j+0]*inv; v.y = acc[4*j+1]*inv;
        v.z = acc[4*j+2]*inv; v.w = acc[4*j+3]*inv;
        *(float4*)(o + 4*j) = v;
    }
}

// ---------------- cross-entropy: per-row -logp[target] ---------------------
__global__ void loss_rows_kernel(const float* __restrict__ logits,
                                 const int* __restrict__ targets) {
    __shared__ float red[256];
    const int row = blockIdx.x;
    const float* lr = logits + (long)row*VV;
    float lmax = -1e30f;
    for (int c = threadIdx.x; c < VV; c += 256) lmax = fmaxf(lmax, lr[c]);
    red[threadIdx.x] = lmax; __syncthreads();
    for (int o = 128; o > 0; o >>= 1) {
        if (threadIdx.x < o) red[threadIdx.x] = fmaxf(red[threadIdx.x], red[threadIdx.x+o]);
        __syncthreads();
    }
    float m = red[0]; __syncthreads();
    float s = 0.f;
    for (int c = threadIdx.x; c < VV; c += 256) s += expf(lr[c] - m);
    red[threadIdx.x] = s; __syncthreads();
    for (int o = 128; o > 0; o >>= 1) {
        if (threadIdx.x < o) red[threadIdx.x] += red[threadIdx.x+o];
        __syncthreads();
    }
    if (threadIdx.x == 0) {
        float lse = m + logf(red[0]);
        g_rowloss[row] = lse - lr[targets[row]];
    }
}

__global__ void loss_reduce_kernel(float* __restrict__ out) {
    __shared__ float red[256];
    float s = 0.f;
    for (int i = threadIdx.x; i < BT; i += 256) s += g_rowloss[i];
    red[threadIdx.x] = s; __syncthreads();
    for (int o = 128; o > 0; o >>= 1) {
        if (threadIdx.x < o) red[threadIdx.x] += red[threadIdx.x+o];
        __syncthreads();
    }
    if (threadIdx.x == 0) *out = red[0] * (1.0f/BT);
}

// ---------------- driver ----------------------------------------------------
extern "C" void kernel_launch(void* const* d_in, const int* in_sizes, int n_in,
                              void* d_out, int out_size) {
    const int*   idx     = (const int*)  d_in[0];
    const int*   targets = (const int*)  d_in[1];
    const float* tok_emb = (const float*)d_in[2];
    const float* pos_emb = (const float*)d_in[3];
    const float* Wq      = (const float*)d_in[4];
    const float* Wk      = (const float*)d_in[5];
    const float* Wv      = (const float*)d_in[6];
    const float* Wproj   = (const float*)d_in[7];
    const float* bproj   = (const float*)d_in[8];
    const float* ln1_g   = (const float*)d_in[9];
    const float* ln1_b   = (const float*)d_in[10];
    const float* ln2_g   = (const float*)d_in[11];
    const float* ln2_b   = (const float*)d_in[12];
    const float* W1      = (const float*)d_in[13];
    const float* b1      = (const float*)d_in[14];
    const float* W2      = (const float*)d_in[15];
    const float* b2      = (const float*)d_in[16];
    const float* Wlm     = (const float*)d_in[17];
    const float* blm     = (const float*)d_in[18];
    float* out = (float*)d_out;

    float* xp;    cudaGetSymbolAddress((void**)&xp,    g_x);
    float* hp;    cudaGetSymbolAddress((void**)&hp,    g_h);
    float* qkvp;  cudaGetSymbolAddress((void**)&qkvp,  g_qkv);
    float* attnp; cudaGetSymbolAddress((void**)&attnp, g_attn);
    float* hidp;  cudaGetSymbolAddress((void**)&hidp,  g_hid);
    float* wqkvp; cudaGetSymbolAddress((void**)&wqkvp, g_wqkv);

    pack_qkv_kernel<<<4096, 256>>>(Wq, Wk, Wv);
    embed_kernel<<<(BT*CC + 255)/256, 256>>>(idx, tok_emb, pos_emb);

    for (int l = 0; l < LL; l++) {
        layernorm_kernel<<<BT, 256>>>(xp, ln1_g + l*CC, ln1_b + l*CC, hp);

        // qkv = h @ Wqkv_packed[l]    [2048,768] x [768,2304]
        gemm_tf32_kernel<false,false,false><<<dim3(QKVN/128, BT/128), 256>>>(
            hp, wqkvp + (long)l*CC*QKVN, nullptr, nullptr, qkvp, BT, QKVN, CC);

        flash_attn_kernel<<<dim3(TT/TQ, BB*HH), TQ>>>(qkvp, attnp);

        // x = x + attn @ Wproj[l] + bproj[l]
        gemm_tf32_kernel<true,false,true><<<dim3(CC/128, BT/128), 256>>>(
            attnp, Wproj + (long)l*CC*CC, bproj + l*CC, xp, xp, BT, CC, CC);

        layernorm_kernel<<<BT, 256>>>(xp, ln2_g + l*CC, ln2_b + l*CC, hp);

        // hid = relu(h @ W1[l] + b1[l])
        gemm_tf32_kernel<true,true,false><<<dim3(HID/128, BT/128), 256>>>(
            hp, W1 + (long)l*CC*HID, b1 + (long)l*HID, nullptr, hidp, BT, HID, CC);

        // x = x + hid @ W2[l] + b2[l]
        gemm_tf32_kernel<true,false,true><<<dim3(CC/128, BT/128), 256>>>(
            hidp, W2 + (long)l*HID*CC, b2 + l*CC, xp, xp, BT, CC, HID);
    }

    // logits = x @ Wlm + blm  -> directly into d_out
    gemm_tf32_kernel<true,false,false><<<dim3(VV/128, BT/128), 256>>>(
        xp, Wlm, blm, nullptr, out, BT, VV, CC);

    loss_rows_kernel<<<BT, 256>>>(out, targets);
    if (out_size >= BT*VV + 1) {
        loss_reduce_kernel<<<1, 256>>>(out + (long)BT*VV);
    } else if (out_size == 1) {
        loss_reduce_kernel<<<1, 256>>>(out);
    }
}

// round 3
// speedup vs baseline: 3.8783x; 1.7801x over previous
#include <cuda_runtime.h>
#include <cuda_bf16.h>
#include <cstdint>

// Problem constants
#define BB 2
#define TT 1024
#define CC 768
#define HH 12
#define DH 64
#define LL 4
#define HID 3072
#define VV 32000
#define BT (BB*TT)          // 2048
#define QKVN (3*CC)         // 2304

// ---------------- scratch (device globals; no cudaMalloc allowed) ----------
__device__ float g_x[BT*CC];          // residual stream
__device__ float g_h[BT*CC];          // layernorm output / rounded x copy
__device__ float g_qkv[BT*QKVN];      // fused qkv output
__device__ float g_attn[BT*CC];       // attention output (concat heads)
__device__ float g_hid[BT*HID];       // MLP hidden
__device__ float g_wqkv[LL*CC*QKVN];  // packed+rounded qkv weights
__device__ float g_wproj[LL*CC*CC];   // rounded
__device__ float g_w1[LL*CC*HID];     // rounded
__device__ float g_w2[LL*HID*CC];     // rounded
__device__ float g_wlm[CC*VV];        // rounded
__device__ float g_rowloss[BT];       // per-row -logp[target]

__device__ __forceinline__ uint32_t f2tf32(float f) {
    uint32_t u;
    asm("cvt.rna.tf32.f32 %0, %1;" : "=r"(u) : "f"(f));
    return u;
}
__device__ __forceinline__ float tf32r(float f) {
    return __uint_as_float(f2tf32(f));
}

// ---------------- weight packing: Wq/Wk/Wv [L,H,C,DH] -> [L][C][3C] (tf32) -
__global__ void pack_qkv_kernel(const float* __restrict__ Wq,
                                const float* __restrict__ Wk,
                                const float* __restrict__ Wv) {
    const long total = (long)LL * CC * QKVN;
    for (long i = (long)blockIdx.x * blockDim.x + threadIdx.x; i < total;
         i += (long)gridDim.x * blockDim.x) {
        int n = (int)(i % QKVN);
        long r = i / QKVN;
        int k = (int)(r % CC);
        int l = (int)(r / CC);
        const float* W; int nn = n;
        if (n < CC)           { W = Wq; }
        else if (n < 2*CC)    { W = Wk; nn = n - CC; }
        else                  { W = Wv; nn = n - 2*CC; }
        int h = nn >> 6, d = nn & 63;
        g_wqkv[i] = tf32r(W[(((long)l*HH + h)*CC + k)*DH + d]);
    }
}

// ---------------- generic tf32 round-copy ----------------------------------
__global__ void round_copy_kernel(const float* __restrict__ src,
                                  float* __restrict__ dst, long n) {
    for (long i = (long)blockIdx.x * blockDim.x + threadIdx.x; i < n;
         i += (long)gridDim.x * blockDim.x)
        dst[i] = tf32r(src[i]);
}

// ---------------- embedding: x = tok_emb[idx] + pos_emb[:T] ----------------
__global__ void embed_kernel(const int* __restrict__ idx,
                             const float* __restrict__ tok,
                             const float* __restrict__ pos) {
    int i = blockIdx.x * blockDim.x + threadIdx.x;
    if (i >= BT*CC) return;
    int c = i % CC;
    int bt = i / CC;
    int t = bt % TT;
    g_x[i] = tok[(long)idx[bt]*CC + c] + pos[(long)t*CC + c];
}

// ---------------- layernorm (rounded output) -------------------------------
__global__ void layernorm_kernel(const float* __restrict__ x,
                                 const float* __restrict__ g,
                                 const float* __restrict__ b,
                                 float* __restrict__ y) {
    __shared__ float rs[256], rs2[256];
    int row = blockIdx.x;
    const float* xr = x + (long)row*CC;
    float s = 0.f, s2 = 0.f;
    for (int c = threadIdx.x; c < CC; c += 256) {
        float v = xr[c];
        s += v; s2 += v*v;
    }
    rs[threadIdx.x] = s; rs2[threadIdx.x] = s2;
    __syncthreads();
    for (int o = 128; o > 0; o >>= 1) {
        if (threadIdx.x < o) {
            rs[threadIdx.x]  += rs[threadIdx.x + o];
            rs2[threadIdx.x] += rs2[threadIdx.x + o];
        }
        __syncthreads();
    }
    float mean = rs[0] * (1.f/CC);
    float var  = rs2[0] * (1.f/CC) - mean*mean;
    float inv  = rsqrtf(var + 1e-5f);
    for (int c = threadIdx.x; c < CC; c += 256) {
        y[(long)row*CC + c] = tf32r((xr[c] - mean) * inv * g[c] + b[c]);
    }
}

// ---------------- TF32 tensor-core GEMM, cp.async 4-stage pipeline ---------
// Inputs MUST be tf32-pre-rounded fp32 -> mma's internal conversion is exact.
// BM=BN=128, BK=16, 256 threads = 8 warps (4x2), warp tile 32x64.
#define ASTRIDE 20    // [m][k] padded, conflict-free frags, 16B-aligned rows
#define BSTRIDE 136   // [k][n] padded
#define STAGES 4

#define CP16(dst, src) asm volatile("cp.async.cg.shared.global [%0], [%1], 16;" :: "r"(dst), "l"(src))

template<bool BIAS, bool RELU, bool RES, bool ROUND>
__global__ void __launch_bounds__(256)
gemm_tf32_kernel(const float* __restrict__ A, const float* __restrict__ B,
                 const float* __restrict__ bias, const float* __restrict__ res,
                 float* __restrict__ C, int M, int N, int K) {
    __shared__ float As[STAGES][128*ASTRIDE];
    __shared__ float Bs[STAGES][16*BSTRIDE];
    const int tid  = threadIdx.x;
    const int wid  = tid >> 5;
    const int lane = tid & 31;
    const int warpM = wid & 3;        // 0..3  -> 32-row slab
    const int warpN = wid >> 2;       // 0..1  -> 64-col slab
    const int gr = lane >> 2;         // 0..7
    const int gc = lane & 3;          // 0..3
    const int m0 = blockIdx.y * 128;
    const int n0 = blockIdx.x * 128;

    float acc[2][8][4];
    #pragma unroll
    for (int mi = 0; mi < 2; mi++)
        #pragma unroll
        for (int ni = 0; ni < 8; ni++)
            #pragma unroll
            for (int j = 0; j < 4; j++) acc[mi][ni][j] = 0.f;

    const int aRow = tid >> 2;          // 0..63
    const int aCol = (tid & 3) << 2;    // 0,4,8,12
    const int bRow = tid >> 5;          // 0..7
    const int bCol = (tid & 31) << 2;   // 0..124

    const float* Ab = A + (long)m0*K;
    const float* Bb = B + n0;
    const int nIter = K >> 4;

    #define ISSUE(it, stg) do {                                            \
        const float* Ag = Ab + ((it) << 4);                                \
        _Pragma("unroll")                                                  \
        for (int r = 0; r < 2; r++) {                                      \
            int row = aRow + r*64;                                         \
            uint32_t d_ = (uint32_t)__cvta_generic_to_shared(              \
                &As[stg][row*ASTRIDE + aCol]);                             \
            CP16(d_, Ag + (long)row*K + aCol);                             \
        }                                                                  \
        const float* Bg = Bb + (long)((it) << 4)*N;                        \
        _Pragma("unroll")                                                  \
        for (int r = 0; r < 2; r++) {                                      \
            int krow = bRow + r*8;                                         \
            uint32_t d_ = (uint32_t)__cvta_generic_to_shared(              \
                &Bs[stg][krow*BSTRIDE + bCol]);                            \
            CP16(d_, Bg + (long)krow*N + bCol);                            \
        }                                                                  \
        asm volatile("cp.async.commit_group;");                            \
    } while (0)

    ISSUE(0, 0); ISSUE(1, 1); ISSUE(2, 2);   // K >= 768 -> nIter >= 48

    for (int it = 0; it < nIter; it++) {
        const int stg = it & (STAGES-1);
        if (it + 2 < nIter)      asm volatile("cp.async.wait_group 2;");
        else if (it + 1 < nIter) asm volatile("cp.async.wait_group 1;");
        else                     asm volatile("cp.async.wait_group 0;");
        __syncthreads();

        #pragma unroll
        for (int kc = 0; kc < 16; kc += 8) {
            uint32_t af[2][4];
            #pragma unroll
            for (int mi = 0; mi < 2; mi++) {
                int row = warpM*32 + mi*16 + gr;
                af[mi][0] = __float_as_uint(As[stg][row*ASTRIDE + kc + gc]);
                af[mi][1] = __float_as_uint(As[stg][(row+8)*ASTRIDE + kc + gc]);
                af[mi][2] = __float_as_uint(As[stg][row*ASTRIDE + kc + gc + 4]);
                af[mi][3] = __float_as_uint(As[stg][(row+8)*ASTRIDE + kc + gc + 4]);
            }
            uint32_t bf[8][2];
            #pragma unroll
            for (int ni = 0; ni < 8; ni++) {
                int col = warpN*64 + ni*8 + gr;
                bf[ni][0] = __float_as_uint(Bs[stg][(kc+gc)*BSTRIDE + col]);
                bf[ni][1] = __float_as_uint(Bs[stg][(kc+gc+4)*BSTRIDE + col]);
            }
            #pragma unroll
            for (int mi = 0; mi < 2; mi++)
                #pragma unroll
                for (int ni = 0; ni < 8; ni++)
                    asm volatile(
                        "mma.sync.aligned.m16n8k8.row.col.f32.tf32.tf32.f32 "
                        "{%0,%1,%2,%3},{%4,%5,%6,%7},{%8,%9},{%0,%1,%2,%3};"
                        : "+f"(acc[mi][ni][0]), "+f"(acc[mi][ni][1]),
                          "+f"(acc[mi][ni][2]), "+f"(acc[mi][ni][3])
                        : "r"(af[mi][0]), "r"(af[mi][1]),
                          "r"(af[mi][2]), "r"(af[mi][3]),
                          "r"(bf[ni][0]), "r"(bf[ni][1]));
        }

        if (it + 3 < nIter) ISSUE(it + 3, (it + 3) & (STAGES-1));
    }
    #undef ISSUE

    // epilogue
    #pragma unroll
    for (int mi = 0; mi < 2; mi++) {
        #pragma unroll
        for (int rr = 0; rr < 2; rr++) {
            long row = m0 + warpM*32 + mi*16 + gr + rr*8;
            #pragma unroll
            for (int ni = 0; ni < 8; ni++) {
                int col = n0 + warpN*64 + ni*8 + gc*2;
                float v0 = acc[mi][ni][rr*2+0];
                float v1 = acc[mi][ni][rr*2+1];
                if (BIAS) { v0 += bias[col]; v1 += bias[col+1]; }
                if (RES)  {
                    float2 rv = *(const float2*)(res + row*N + col);
                    v0 += rv.x; v1 += rv.y;
                }
                if (RELU) { v0 = fmaxf(v0, 0.f); v1 = fmaxf(v1, 0.f); }
                if (ROUND){ v0 = tf32r(v0); v1 = tf32r(v1); }
                float2 ov; ov.x = v0; ov.y = v1;
                *(float2*)(C + row*N + col) = ov;
            }
        }
    }
}

// ---------------- flash attention, 2-way split-K ---------------------------
// 128 threads: half 0 (tid<64) does tiles [0,nT/2), half 1 tiles [nT/2,nT).
// nT = (q0+64)/16 is always a multiple of 4 -> equal trip counts, no ragged.
#define TQ 64
#define TS 16
__global__ void __launch_bounds__(128)
flash_attn_kernel(const float* __restrict__ qkv, float* __restrict__ out) {
    __shared__ float KV[2][2][TS*DH];   // [k/v][half][s*DH+d]  16KB
    __shared__ float ml[2][TQ];         // m,l of half 1
    const int q0 = (gridDim.x - 1 - blockIdx.x) * TQ;  // longest first
    const int bh = blockIdx.y;
    const int b  = bh / HH;
    const int h  = bh % HH;
    const int tid  = threadIdx.x;
    const int tq   = tid & 63;
    const int half = tid >> 6;
    const int t = q0 + tq;
    const float* base = qkv + (long)b*TT*QKVN;

    float q[DH];
    {
        const float4* qr = (const float4*)(base + (long)t*QKVN + h*DH);
        #pragma unroll
        for (int j = 0; j < DH/4; j++) {
            float4 v = qr[j];
            q[4*j+0] = v.x; q[4*j+1] = v.y; q[4*j+2] = v.z; q[4*j+3] = v.w;
        }
    }
    float acc[DH];
    #pragma unroll
    for (int j = 0; j < DH; j++) acc[j] = 0.f;
    float m = -1e30f, l = 0.f;

    const int nT = (q0 + TQ) / TS;
    const int nHalf = nT >> 1;
    const int tile0 = half * nHalf;

    for (int jt = 0; jt < nHalf; jt++) {
        const int s0 = (tile0 + jt) * TS;
        __syncthreads();
        #pragma unroll
        for (int i = 0; i < 4; i++) {
            int idx = tq + i*64;             // 0..255 float4s
            int s  = idx >> 4;
            int d4 = (idx & 15) << 2;
            const float* kp = base + (long)(s0+s)*QKVN + CC + h*DH + d4;
            *(float4*)&KV[0][half][s*DH + d4] = *(const float4*)kp;
            *(float4*)&KV[1][half][s*DH + d4] = *(const float4*)(kp + CC);
        }
        __syncthreads();

        float sc[TS];
        float tmax = -1e30f;
        #pragma unroll
        for (int s = 0; s < TS; s++) {
            float d0 = 0.f, d1 = 0.f, d2 = 0.f, d3 = 0.f;
            const float* kr = &KV[0][half][s*DH];
            #pragma unroll
            for (int j = 0; j < DH; j += 4) {
                d0 += q[j+0] * kr[j+0];
                d1 += q[j+1] * kr[j+1];
                d2 += q[j+2] * kr[j+2];
                d3 += q[j+3] * kr[j+3];
            }
            float d = (d0 + d1) + (d2 + d3);
            sc[s] = (s0 + s <= t) ? d * 0.125f : -1e30f;
            tmax = fmaxf(tmax, sc[s]);
        }
        if (tmax > -1e29f) {                 // tile contributes
            float m_new = fmaxf(m, tmax);
            float alpha = __expf(m - m_new);
            l *= alpha;
            #pragma unroll
            for (int j = 0; j < DH; j++) acc[j] *= alpha;
            #pragma unroll
            for (int s = 0; s < TS; s++) {
                float p = (sc[s] > -1e29f) ? __expf(sc[s] - m_new) : 0.f;
                l += p;
                const float* vr = &KV[1][half][s*DH];
                #pragma unroll
                for (int j = 0; j < DH; j++) acc[j] += p * vr[j];
            }
            m = m_new;
        }
    }

    // merge: half 1 publishes, half 0 combines + writes (tf32-rounded)
    __syncthreads();
    float* xch = (float*)KV;                // 4096 floats == 64x64
    if (half == 1) {
        ml[0][tq] = m; ml[1][tq] = l;
        #pragma unroll
        for (int j = 0; j < DH; j++)
            xch[tq*DH + ((j + tq) & 63)] = acc[j];   // bank-swizzled
    }
    __syncthreads();
    if (half == 0) {
        float m1 = ml[0][tq], l1 = ml[1][tq];
        float ms = fmaxf(m, m1);
        float a0 = __expf(m - ms);
        float a1 = __expf(m1 - ms);
        float inv = 1.0f / (l*a0 + l1*a1);
        float* o = out + ((long)b*TT + t)*CC + h*DH;
        #pragma unroll
        for (int j = 0; j < DH; j += 4) {
            float4 v;
            v.x = tf32r((acc[j+0]*a0 + xch[tq*DH + ((j+0+tq)&63)]*a1) * inv);
            v.y = tf32r((acc[j+1]*a0 + xch[tq*DH + ((j+1+tq)&63)]*a1) * inv);
            v.z = tf32r((acc[j+2]*a0 + xch[tq*DH + ((j+2+tq)&63)]*a1) * inv);
            v.w = tf32r((acc[j+3]*a0 + xch[tq*DH + ((j+3+tq)&63)]*a1) * inv);
            *(float4*)(o + j) = v;
        }
    }
}

// ---------------- cross-entropy: single-pass online softmax ----------------
__global__ void loss_rows_kernel(const float* __restrict__ logits,
                                 const int* __restrict__ targets) {
    __shared__ float sm[256], ss[256];
    const int row = blockIdx.x;
    const float* lr = logits + (long)row*VV;
    float m = -1e30f, s = 0.f;
    for (int c = threadIdx.x; c < VV; c += 256) {
        float v = lr[c];
        if (v <= m) s += __expf(v - m);
        else { s = s*__expf(m - v) + 1.f; m = v; }
    }
    sm[threadIdx.x] = m; ss[threadIdx.x] = s;
    __syncthreads();
    for (int o = 128; o > 0; o >>= 1) {
        if (threadIdx.x < o) {
            float m2 = sm[threadIdx.x+o], s2 = ss[threadIdx.x+o];
            float mm = fmaxf(sm[threadIdx.x], m2);
            ss[threadIdx.x] = ss[threadIdx.x]*__expf(sm[threadIdx.x]-mm)
                            + s2*__expf(m2-mm);
            sm[threadIdx.x] = mm;
        }
        __syncthreads();
    }
    if (threadIdx.x == 0) {
        float lse = sm[0] + logf(ss[0]);
        g_rowloss[row] = lse - lr[targets[row]];
    }
}

__global__ void loss_reduce_kernel(float* __restrict__ out) {
    __shared__ float red[256];
    float s = 0.f;
    for (int i = threadIdx.x; i < BT; i += 256) s += g_rowloss[i];
    red[threadIdx.x] = s; __syncthreads();
    for (int o = 128; o > 0; o >>= 1) {
        if (threadIdx.x < o) red[threadIdx.x] += red[threadIdx.x+o];
        __syncthreads();
    }
    if (threadIdx.x == 0) *out = red[0] * (1.0f/BT);
}

// ---------------- driver ----------------------------------------------------
extern "C" void kernel_launch(void* const* d_in, const int* in_sizes, int n_in,
                              void* d_out, int out_size) {
    const int*   idx     = (const int*)  d_in[0];
    const int*   targets = (const int*)  d_in[1];
    const float* tok_emb = (const float*)d_in[2];
    const float* pos_emb = (const float*)d_in[3];
    const float* Wq      = (const float*)d_in[4];
    const float* Wk      = (const float*)d_in[5];
    const float* Wv      = (const float*)d_in[6];
    const float* Wproj   = (const float*)d_in[7];
    const float* bproj   = (const float*)d_in[8];
    const float* ln1_g   = (const float*)d_in[9];
    const float* ln1_b   = (const float*)d_in[10];
    const float* ln2_g   = (const float*)d_in[11];
    const float* ln2_b   = (const float*)d_in[12];
    const float* W1      = (const float*)d_in[13];
    const float* b1      = (const float*)d_in[14];
    const float* W2      = (const float*)d_in[15];
    const float* b2      = (const float*)d_in[16];
    const float* Wlm     = (const float*)d_in[17];
    const float* blm     = (const float*)d_in[18];
    float* out = (float*)d_out;

    float* xp;    cudaGetSymbolAddress((void**)&xp,    g_x);
    float* hp;    cudaGetSymbolAddress((void**)&hp,    g_h);
    float* qkvp;  cudaGetSymbolAddress((void**)&qkvp,  g_qkv);
    float* attnp; cudaGetSymbolAddress((void**)&attnp, g_attn);
    float* hidp;  cudaGetSymbolAddress((void**)&hidp,  g_hid);
    float* wqkvp; cudaGetSymbolAddress((void**)&wqkvp, g_wqkv);
    float* wprojp;cudaGetSymbolAddress((void**)&wprojp,g_wproj);
    float* w1p;   cudaGetSymbolAddress((void**)&w1p,   g_w1);
    float* w2p;   cudaGetSymbolAddress((void**)&w2p,   g_w2);
    float* wlmp;  cudaGetSymbolAddress((void**)&wlmp,  g_wlm);

    pack_qkv_kernel<<<2048, 256>>>(Wq, Wk, Wv);
    round_copy_kernel<<<2048, 256>>>(Wproj, wprojp, (long)LL*CC*CC);
    round_copy_kernel<<<2048, 256>>>(W1,    w1p,    (long)LL*CC*HID);
    round_copy_kernel<<<2048, 256>>>(W2,    w2p,    (long)LL*HID*CC);
    round_copy_kernel<<<4096, 256>>>(Wlm,   wlmp,   (long)CC*VV);
    embed_kernel<<<(BT*CC + 255)/256, 256>>>(idx, tok_emb, pos_emb);

    for (int l = 0; l < LL; l++) {
        layernorm_kernel<<<BT, 256>>>(xp, ln1_g + l*CC, ln1_b + l*CC, hp);

        // qkv = h @ Wqkv[l]    [2048,768]x[768,2304]
        gemm_tf32_kernel<false,false,false,false><<<dim3(QKVN/128, BT/128), 256>>>(
            hp, wqkvp + (long)l*CC*QKVN, nullptr, nullptr, qkvp, BT, QKVN, CC);

        flash_attn_kernel<<<dim3(TT/TQ, BB*HH), 128>>>(qkvp, attnp);

        // x = x + attn @ Wproj[l] + bproj[l]
        gemm_tf32_kernel<true,false,true,false><<<dim3(CC/128, BT/128), 256>>>(
            attnp, wprojp + (long)l*CC*CC, bproj + l*CC, xp, xp, BT, CC, CC);

        layernorm_kernel<<<BT, 256>>>(xp, ln2_g + l*CC, ln2_b + l*CC, hp);

        // hid = relu(h @ W1[l] + b1[l])  (rounded output: feeds next GEMM)
        gemm_tf32_kernel<true,true,false,true><<<dim3(HID/128, BT/128), 256>>>(
            hp, w1p + (long)l*CC*HID, b1 + (long)l*HID, nullptr, hidp, BT, HID, CC);

        // x = x + hid @ W2[l] + b2[l]
        gemm_tf32_kernel<true,false,true,false><<<dim3(CC/128, BT/128), 256>>>(
            hidp, w2p + (long)l*HID*CC, b2 + l*CC, xp, xp, BT, CC, HID);
    }

    // rounded copy of x for the LM head A-operand
    round_copy_kernel<<<2048, 256>>>(xp, hp, (long)BT*CC);

    // logits = x @ Wlm + blm -> d_out
    gemm_tf32_kernel<true,false,false,false><<<dim3(VV/128, BT/128), 256>>>(
        hp, wlmp, blm, nullptr, out, BT, VV, CC);

    loss_rows_kernel<<<BT, 256>>>(out, targets);
    if (out_size >= BT*VV + 1) {
        loss_reduce_kernel<<<1, 256>>>(out + (long)BT*VV);
    } else if (out_size == 1) {
        loss_reduce_kernel<<<1, 256>>>(out);
    }
}